// round 3
// baseline (speedup 1.0000x reference)
#include <cuda_runtime.h>
#include <cuda_bf16.h>
#include <math.h>

// Problem constants
#define B_ 256
#define F_ 8
#define S_ 200
#define D_ 64
#define H_ 36
#define BF_ (B_ * F_)   // 2048
#define EPS_ 0.001f

typedef unsigned long long u64;

// ---------------- scratch (device globals; no allocations allowed) ----------
__device__ float g_A[F_ * D_ * H_];    // W1 - W3   [f][d][h]
__device__ float g_Bq[F_ * D_ * H_];   // W2 + W3   [f][d][h]
__device__ float g_h[(size_t)BF_ * S_ * H_];   // h TRANSPOSED: [bf][h][s]
__device__ float g_sum[F_ * H_];
__device__ float g_sumsq[F_ * H_];

// ---------------- packed f32x2 helpers (Blackwell FFMA2) --------------------
__device__ __forceinline__ u64 pack2(float x, float y) {
    u64 r;
    asm("mov.b64 %0, {%1, %2};" : "=l"(r) : "f"(x), "f"(y));
    return r;
}
__device__ __forceinline__ u64 fma2(u64 a, u64 b, u64 c) {
    u64 d;
    asm("fma.rn.f32x2 %0, %1, %2, %3;" : "=l"(d) : "l"(a), "l"(b), "l"(c));
    return d;
}
__device__ __forceinline__ float2 unpack2(u64 v) {
    float2 r;
    asm("mov.b64 {%0, %1}, %2;" : "=f"(r.x), "=f"(r.y) : "l"(v));
    return r;
}

// ---------------- kernel 0: fold W_h, zero accumulators ---------------------
__global__ void k_prep(const float* __restrict__ Wh) {
    int f = blockIdx.x;
    for (int i = threadIdx.x; i < D_ * H_; i += blockDim.x) {
        int d = i / H_, h = i % H_;
        float w1 = Wh[(f * 3 * D_ + d) * H_ + h];
        float w2 = Wh[(f * 3 * D_ + D_ + d) * H_ + h];
        float w3 = Wh[(f * 3 * D_ + 2 * D_ + d) * H_ + h];
        g_A[f * D_ * H_ + i]  = w1 - w3;
        g_Bq[f * D_ * H_ + i] = w2 + w3;
    }
    if (blockIdx.x == 0) {
        for (int i = threadIdx.x; i < F_ * H_; i += blockDim.x) {
            g_sum[i] = 0.f;
            g_sumsq[i] = 0.f;
        }
    }
}

// ---------------- kernel 1: h = key @ A + (q @ Bq + b_h), fused stats -------
// one block per (b,f); 128 threads; thread t owns rows s=2t, 2t+1 (t<100)
__device__ __forceinline__ void dstep(const float* A_sm, int d, float k0, float k1,
                                      u64* acc0, u64* acc1) {
    u64 kv0 = pack2(k0, k0);
    u64 kv1 = pack2(k1, k1);
    const ulonglong2* ar = reinterpret_cast<const ulonglong2*>(A_sm + d * H_);
#pragma unroll
    for (int j = 0; j < 9; ++j) {
        ulonglong2 av = ar[j];
        acc0[2 * j]     = fma2(kv0, av.x, acc0[2 * j]);
        acc0[2 * j + 1] = fma2(kv0, av.y, acc0[2 * j + 1]);
        acc1[2 * j]     = fma2(kv1, av.x, acc1[2 * j]);
        acc1[2 * j + 1] = fma2(kv1, av.y, acc1[2 * j + 1]);
    }
}

__global__ __launch_bounds__(128) void k_hgemm(const float* __restrict__ q,
                                               const float* __restrict__ key,
                                               const float* __restrict__ bh) {
    __shared__ __align__(16) float A_sm[D_ * H_];
    __shared__ __align__(16) float c_sm[H_ + 4];
    __shared__ float redS[H_ * 128];   // per-h partial sums
    __shared__ float redQ[H_ * 128];   // per-h partial sumsq
    int bf = blockIdx.x;
    int f = bf & 7;
    int t = threadIdx.x;

    for (int i = t; i < D_ * H_; i += 128) A_sm[i] = g_A[f * D_ * H_ + i];

    if (t < H_) {
        // c0[h] = b_h[f,h] + sum_d q[b,f,d] * Bq[f,d,h]
        const float* qq = q + bf * D_;
        const float* Bq = g_Bq + f * D_ * H_ + t;
        float a0 = 0.f, a1 = 0.f, a2 = 0.f, a3 = 0.f;
#pragma unroll
        for (int d = 0; d < D_; d += 4) {
            a0 += qq[d]     * Bq[d * H_];
            a1 += qq[d + 1] * Bq[(d + 1) * H_];
            a2 += qq[d + 2] * Bq[(d + 2) * H_];
            a3 += qq[d + 3] * Bq[(d + 3) * H_];
        }
        c_sm[t] = bh[f * H_ + t] + ((a0 + a1) + (a2 + a3));
    }
    __syncthreads();

    bool active = (t < 100);
    int tt = active ? t : 99;           // keep warps uniform
    int s0 = tt * 2;
    const float4* kr0 = reinterpret_cast<const float4*>(key + (size_t)bf * S_ * D_ + (size_t)s0 * D_);
    const float4* kr1 = kr0 + (D_ / 4);

    u64 acc0[18], acc1[18];
#pragma unroll
    for (int j = 0; j < 18; ++j) {
        u64 cp = *reinterpret_cast<const u64*>(&c_sm[2 * j]);
        acc0[j] = cp;
        acc1[j] = cp;
    }

#pragma unroll 2
    for (int dq = 0; dq < 16; ++dq) {
        float4 k0 = kr0[dq];
        float4 k1 = kr1[dq];
        int d = dq * 4;
        dstep(A_sm, d + 0, k0.x, k1.x, acc0, acc1);
        dstep(A_sm, d + 1, k0.y, k1.y, acc0, acc1);
        dstep(A_sm, d + 2, k0.z, k1.z, acc0, acc1);
        dstep(A_sm, d + 3, k0.w, k1.w, acc0, acc1);
    }

    // Store h transposed ([h][s], coalesced float2) + stage stats partials
    float* hT = g_h + (size_t)bf * (S_ * H_);
#pragma unroll
    for (int j = 0; j < 18; ++j) {
        float2 a = unpack2(acc0[j]);   // row s0:   h=2j (x), h=2j+1 (y)
        float2 b = unpack2(acc1[j]);   // row s0+1
        redS[(2 * j)     * 128 + t] = active ? (a.x + b.x) : 0.f;
        redS[(2 * j + 1) * 128 + t] = active ? (a.y + b.y) : 0.f;
        redQ[(2 * j)     * 128 + t] = active ? (a.x * a.x + b.x * b.x) : 0.f;
        redQ[(2 * j + 1) * 128 + t] = active ? (a.y * a.y + b.y * b.y) : 0.f;
        if (active) {
            *reinterpret_cast<float2*>(&hT[(2 * j) * S_ + s0])     = make_float2(a.x, b.x);
            *reinterpret_cast<float2*>(&hT[(2 * j + 1) * S_ + s0]) = make_float2(a.y, b.y);
        }
    }
    __syncthreads();

    // warp w reduces h rows [9w, 9w+9): 4 smem loads + shfl tree, leader atomics
    int wid = t >> 5, lane = t & 31;
#pragma unroll
    for (int hh = 0; hh < 9; ++hh) {
        int h = wid * 9 + hh;
        float s = redS[h * 128 + lane] + redS[h * 128 + lane + 32]
                + redS[h * 128 + lane + 64] + redS[h * 128 + lane + 96];
        float qv = redQ[h * 128 + lane] + redQ[h * 128 + lane + 32]
                 + redQ[h * 128 + lane + 64] + redQ[h * 128 + lane + 96];
#pragma unroll
        for (int off = 16; off >= 1; off >>= 1) {
            s  += __shfl_xor_sync(0xffffffffu, s, off);
            qv += __shfl_xor_sync(0xffffffffu, qv, off);
        }
        if (lane == 0) {
            atomicAdd(&g_sum[f * H_ + h], s);
            atomicAdd(&g_sumsq[f * H_ + h], qv);
        }
    }
}

// ---------------- kernel 2: finalize stats (inline) + gate + softmax + attn -
__global__ __launch_bounds__(256) void k_attend(const float* __restrict__ key,
                                                const float* __restrict__ alpha,
                                                const float* __restrict__ Wo,
                                                const float* __restrict__ bo,
                                                const int* __restrict__ seq,
                                                float* __restrict__ out) {
    __shared__ float mean_sm[36], rstd_sm[36], wo_sm[36];
    __shared__ float attn_sm[S_];
    __shared__ float warp_mx[8], warp_sm[8];
    __shared__ float red[256];
    int bf = blockIdx.x;
    int f = bf & 7;
    int t = threadIdx.x;
    int wid = t >> 5, lane = t & 31;

    if (t < 36) {
        float n = (float)(B_ * S_);
        float m = g_sum[f * 36 + t] / n;
        float v = g_sumsq[f * 36 + t] / n - m * m;
        v = fmaxf(v, 0.f);
        mean_sm[t] = m;
        rstd_sm[t] = rsqrtf(v + EPS_);
        wo_sm[t]   = Wo[f * 36 + t];
    }
    float al = alpha[f];
    float bof = bo[f];
    int n = seq[bf];
    __syncthreads();

    float score = -INFINITY;
    if (t < S_) {
        const float* hT = g_h + (size_t)bf * S_ * H_;
        float sc = 0.f;
#pragma unroll
        for (int h = 0; h < 36; ++h) {
            float x = hT[h * S_ + t];           // coalesced across threads
            float z = (x - mean_sm[h]) * rstd_sm[h];
            float p = 1.f / (1.f + __expf(-z));
            sc += (al * (1.f - p) + p) * x * wo_sm[h];
        }
        if (t < n) score = sc + bof;
        else score = -INFINITY;
    }

    // block max via warp shfl + leaders
    float m = score;
#pragma unroll
    for (int off = 16; off >= 1; off >>= 1)
        m = fmaxf(m, __shfl_xor_sync(0xffffffffu, m, off));
    if (lane == 0) warp_mx[wid] = m;
    __syncthreads();
    float bm = warp_mx[0];
#pragma unroll
    for (int k = 1; k < 8; ++k) bm = fmaxf(bm, warp_mx[k]);

    float e = __expf(score - bm);   // -inf -> 0
    float se = e;
#pragma unroll
    for (int off = 16; off >= 1; off >>= 1)
        se += __shfl_xor_sync(0xffffffffu, se, off);
    if (lane == 0) warp_sm[wid] = se;
    __syncthreads();
    float tot = warp_sm[0] + warp_sm[1] + warp_sm[2] + warp_sm[3]
              + warp_sm[4] + warp_sm[5] + warp_sm[6] + warp_sm[7];
    if (t < S_) attn_sm[t] = e / tot;
    __syncthreads();

    // out[d] = sum_s attn[s] * key[b,f,s,d]
    int d = t & 63;
    int jg = t >> 6;               // 0..3 -> s chunks of 50
    const float* kb = key + (size_t)bf * S_ * D_ + d;
    float acc = 0.f;
#pragma unroll 5
    for (int s = jg * 50; s < jg * 50 + 50; ++s) acc += attn_sm[s] * kb[s * D_];
    red[t] = acc;
    __syncthreads();
    if (t < 64) out[bf * 64 + t] = red[t] + red[t + 64] + red[t + 128] + red[t + 192];
}

// ---------------- launch ----------------------------------------------------
extern "C" void kernel_launch(void* const* d_in, const int* in_sizes, int n_in,
                              void* d_out, int out_size) {
    const float* query = (const float*)d_in[0];
    const float* key   = (const float*)d_in[1];
    const float* W_h   = (const float*)d_in[2];
    const float* b_h   = (const float*)d_in[3];
    const float* alpha = (const float*)d_in[4];
    const float* W_o   = (const float*)d_in[5];
    const float* b_o   = (const float*)d_in[6];
    const int*   seq   = (const int*)d_in[7];
    float* out = (float*)d_out;

    k_prep<<<F_, 256>>>(W_h);
    k_hgemm<<<BF_, 128>>>(query, key, b_h);
    k_attend<<<BF_, 256>>>(key, alpha, W_o, b_o, seq, out);
}